// round 11
// baseline (speedup 1.0000x reference)
#include <cuda_runtime.h>
#include <cuda_bf16.h>

// Haar DWT (pywt 'haar', torch-style flipped filters + cross-correlation):
//   a=x[h,w] b=x[h,w+1] c=x[h+1,w] d=x[h+1,w+1]  (zero pad right/bottom)
//   LL=.5(a+b+c+d)  LH=.5(a+b-c-d)  HL=.5(a-b+c-d)  HH=.5(a-b-c+d)
// out[b, 4c+k, h, w]  ->  plane index 4*(b*C+c)+k
//
// R11: endpoint of the finer-CTA trend (256thr: 78.7% DRAM -> 128thr: 79.9%).
// 64-thread blocks: one row per CTA, warp = column group. 131072 CTAs.
// Same 512B/warp access pattern as R6/R8 (2x LDG.128 + 4x STG.128/thread,
// shuffle neighbors), 27 regs.

#define DWT_W 256
#define DWT_H 256
#define W4    (DWT_W / 4)
#define PLANE4 ((size_t)DWT_H * W4)
#define FULL  0xffffffffu

// block (32, 2): 2 warps = 1 row x 2 column groups. grid: (H, B*C)
__global__ __launch_bounds__(64)
void haar_dwt_kernel(const float* __restrict__ x, float* __restrict__ out)
{
    const int lane = threadIdx.x;                 // 0..31
    const int g    = threadIdx.y;                 // column group: 0 -> [0,128), 1 -> [128,256)
    const int h    = blockIdx.x;                  // output row
    const int bc   = blockIdx.y;                  // b*C + c

    const float*  xp  = x + (size_t)bc * DWT_H * DWT_W;
    const float4* xp4 = (const float4*)xp;

    const int  col4    = 32 * g + lane;           // float4 column 0..63
    const bool has_bot = (h < DWT_H - 1);

    // ---- front-batched loads: 2 independent 512B/warp LDG.128 ----
    float4 top = xp4[h * W4 + col4];
    float4 bot = has_bot ? xp4[(h + 1) * W4 + col4]
                         : make_float4(0.f, 0.f, 0.f, 0.f);

    // ---- horizontal neighbors via shuffle; seam handled by lane 31 ----
    float tn = __shfl_down_sync(FULL, top.x, 1);
    float bn = __shfl_down_sync(FULL, bot.x, 1);
    if (lane == 31) {
        if (g == 0) {           // neighbor is col 128 (first elem of group 1)
            tn = __ldg(&xp[h * DWT_W + 128]);
            bn = has_bot ? __ldg(&xp[(h + 1) * DWT_W + 128]) : 0.0f;
        } else {                // neighbor is col 256 -> zero pad
            tn = 0.0f;
            bn = 0.0f;
        }
    }

    // ---- horizontal sums/diffs shared by the 4 subbands ----
    const float ts0 = top.x + top.y, ts1 = top.y + top.z, ts2 = top.z + top.w, ts3 = top.w + tn;
    const float td0 = top.x - top.y, td1 = top.y - top.z, td2 = top.z - top.w, td3 = top.w - tn;
    const float bs0 = bot.x + bot.y, bs1 = bot.y + bot.z, bs2 = bot.z + bot.w, bs3 = bot.w + bn;
    const float bd0 = bot.x - bot.y, bd1 = bot.y - bot.z, bd2 = bot.z - bot.w, bd3 = bot.w - bn;

    float4* ob = (float4*)out + (size_t)(4 * bc) * PLANE4;
    const size_t oidx = (size_t)h * W4 + col4;

    float4 v;
    v.x = 0.5f * (ts0 + bs0); v.y = 0.5f * (ts1 + bs1);
    v.z = 0.5f * (ts2 + bs2); v.w = 0.5f * (ts3 + bs3);
    __stcs(ob + oidx, v);                                   // LL

    v.x = 0.5f * (ts0 - bs0); v.y = 0.5f * (ts1 - bs1);
    v.z = 0.5f * (ts2 - bs2); v.w = 0.5f * (ts3 - bs3);
    __stcs(ob + PLANE4 + oidx, v);                          // LH

    v.x = 0.5f * (td0 + bd0); v.y = 0.5f * (td1 + bd1);
    v.z = 0.5f * (td2 + bd2); v.w = 0.5f * (td3 + bd3);
    __stcs(ob + 2 * PLANE4 + oidx, v);                      // HL

    v.x = 0.5f * (td0 - bd0); v.y = 0.5f * (td1 - bd1);
    v.z = 0.5f * (td2 - bd2); v.w = 0.5f * (td3 - bd3);
    __stcs(ob + 3 * PLANE4 + oidx, v);                      // HH
}

extern "C" void kernel_launch(void* const* d_in, const int* in_sizes, int n_in,
                              void* d_out, int out_size)
{
    const float* x = (const float*)d_in[0];
    float* out = (float*)d_out;

    const int n_planes = in_sizes[0] / (DWT_H * DWT_W);   // B*C = 512

    dim3 block(32, 2, 1);
    dim3 grid(DWT_H, n_planes, 1);
    haar_dwt_kernel<<<grid, block>>>(x, out);
}